// round 7
// baseline (speedup 1.0000x reference)
#include <cuda_runtime.h>
#include <cstdint>

// Problem constants
#define BATCH 2
#define NCAM  6
#define DD    48
#define HH    28
#define WW    60
#define CC    64
#define GX    128
#define GY    128

// ---------------------------------------------------------------------------
// One fused kernel. Grid: (GY, BATCH) = 256 blocks. Block: 256 threads.
//   warp (tid>>5) = channel group cg (channels cg*8..cg*8+7)
//   lane (tid&31) = x within a 32-wide tile; block covers 4 tiles (x = 0..127)
//
// Phase 0: lanes 0..5 compute M = K @ inv(l2s)[0:3,:] for 6 cams -> smem
// Phase 1: 96 threads run an EXACT interval validity test per (tile, combo)
//          (u,v,d affine in gx => u/d monotone Mobius on the tile when d>0,
//           so endpoint evaluation bounds all 32 lanes). Deterministic
//          ballot/prefix compaction of survivors into sm_list.
// Phase 2: loop over surviving entries only; per-lane projection + trilinear
//          gather (identical math to the validated kernel), accumulate into
//          per-tile register accumulators.
// Phase 3: coalesced stores out[b][c][y][x].
// ---------------------------------------------------------------------------
__global__ void __launch_bounds__(256)
bev_kernel(const float* __restrict__ frustum,
           const float* __restrict__ intr,
           const float* __restrict__ l2s,
           float* __restrict__ out) {
    __shared__ float sm_M[NCAM * 12];
    __shared__ int   sm_list[96];
    __shared__ int   sm_wcnt[3];

    const int tid = threadIdx.x;
    const int y   = blockIdx.x;
    const int b   = blockIdx.y;

    // ---- Phase 0: per-block matrix prep (lanes 0..5) ----
    if (tid < NCAM) {
        const int idx = b * NCAM + tid;
        const float* m = l2s + idx * 16;   // row-major 4x4
        const float* K = intr + idx * 9;   // row-major 3x3

        float inv[16];
        inv[0]  =  m[5]*m[10]*m[15] - m[5]*m[11]*m[14] - m[9]*m[6]*m[15] + m[9]*m[7]*m[14] + m[13]*m[6]*m[11] - m[13]*m[7]*m[10];
        inv[4]  = -m[4]*m[10]*m[15] + m[4]*m[11]*m[14] + m[8]*m[6]*m[15] - m[8]*m[7]*m[14] - m[12]*m[6]*m[11] + m[12]*m[7]*m[10];
        inv[8]  =  m[4]*m[9]*m[15]  - m[4]*m[11]*m[13] - m[8]*m[5]*m[15] + m[8]*m[7]*m[13] + m[12]*m[5]*m[11] - m[12]*m[7]*m[9];
        inv[12] = -m[4]*m[9]*m[14]  + m[4]*m[10]*m[13] + m[8]*m[5]*m[14] - m[8]*m[6]*m[13] - m[12]*m[5]*m[10] + m[12]*m[6]*m[9];
        inv[1]  = -m[1]*m[10]*m[15] + m[1]*m[11]*m[14] + m[9]*m[2]*m[15] - m[9]*m[3]*m[14] - m[13]*m[2]*m[11] + m[13]*m[3]*m[10];
        inv[5]  =  m[0]*m[10]*m[15] - m[0]*m[11]*m[14] - m[8]*m[2]*m[15] + m[8]*m[3]*m[14] + m[12]*m[2]*m[11] - m[12]*m[3]*m[10];
        inv[9]  = -m[0]*m[9]*m[15]  + m[0]*m[11]*m[13] + m[8]*m[1]*m[15] - m[8]*m[3]*m[13] - m[12]*m[1]*m[11] + m[12]*m[3]*m[9];
        inv[13] =  m[0]*m[9]*m[14]  - m[0]*m[10]*m[13] - m[8]*m[1]*m[14] + m[8]*m[2]*m[13] + m[12]*m[1]*m[10] - m[12]*m[2]*m[9];
        inv[2]  =  m[1]*m[6]*m[15]  - m[1]*m[7]*m[14]  - m[5]*m[2]*m[15] + m[5]*m[3]*m[14] + m[13]*m[2]*m[7]  - m[13]*m[3]*m[6];
        inv[6]  = -m[0]*m[6]*m[15]  + m[0]*m[7]*m[14]  + m[4]*m[2]*m[15] - m[4]*m[3]*m[14] - m[12]*m[2]*m[7]  + m[12]*m[3]*m[6];
        inv[10] =  m[0]*m[5]*m[15]  - m[0]*m[7]*m[13]  - m[4]*m[1]*m[15] + m[4]*m[3]*m[13] + m[12]*m[1]*m[7]  - m[12]*m[3]*m[5];
        inv[14] = -m[0]*m[5]*m[14]  + m[0]*m[6]*m[13]  + m[4]*m[1]*m[14] - m[4]*m[2]*m[13] - m[12]*m[1]*m[6]  + m[12]*m[2]*m[5];
        inv[3]  = -m[1]*m[6]*m[11]  + m[1]*m[7]*m[10]  + m[5]*m[2]*m[11] - m[5]*m[3]*m[10] - m[9]*m[2]*m[7]   + m[9]*m[3]*m[6];
        inv[7]  =  m[0]*m[6]*m[11]  - m[0]*m[7]*m[10]  - m[4]*m[2]*m[11] + m[4]*m[3]*m[10] + m[8]*m[2]*m[7]   - m[8]*m[3]*m[6];
        inv[11] = -m[0]*m[5]*m[11]  + m[0]*m[7]*m[9]   + m[4]*m[1]*m[11] - m[4]*m[3]*m[9]  - m[8]*m[1]*m[7]   + m[8]*m[3]*m[5];
        inv[15] =  m[0]*m[5]*m[10]  - m[0]*m[6]*m[9]   - m[4]*m[1]*m[10] + m[4]*m[2]*m[9]  + m[8]*m[1]*m[6]   - m[8]*m[2]*m[5];

        float det = m[0]*inv[0] + m[1]*inv[4] + m[2]*inv[8] + m[3]*inv[12];
        float rdet = 1.0f / det;
        #pragma unroll
        for (int i = 0; i < 16; i++) inv[i] *= rdet;

        float* M = sm_M + tid * 12;
        #pragma unroll
        for (int r = 0; r < 3; r++) {
            #pragma unroll
            for (int c = 0; c < 4; c++) {
                M[r * 4 + c] = K[r*3 + 0] * inv[0*4 + c]
                             + K[r*3 + 1] * inv[1*4 + c]
                             + K[r*3 + 2] * inv[2*4 + c];
            }
        }
    }
    __syncthreads();

    const float gy = -47.625f + 0.75f * (float)y;

    // ---- Phase 1: exact interval test per (tile, combo) ----
    // Conservative margins: DLO/DHI slightly widened, uv bounds +-2e-3.
    // All validity boundaries have weight -> 0, so margins are harmless.
    const float DLO = 0.9770f;   // d > 2 - 48/47 = 0.97872 (widened down)
    const float DHI = 51.05f;    // d < 2 + 48*48/47 = 51.021 (widened up)

    int pass = 0;
    const int myw = tid >> 5;
    if (tid < 96) {
        const int combo = tid >> 2;       // cam*4 + z
        const int tile  = tid & 3;
        const int cam   = combo >> 2;
        const int zz    = combo & 3;
        const float gz  = -3.0f + 2.0f * (float)zz;
        const float* M  = &sm_M[cam * 12];
        const float gxa = -47.625f + 0.75f * (float)(tile * 32);
        const float gxb = -47.625f + 0.75f * (float)(tile * 32 + 31);
        const float uc = M[1]*gy + M[2]*gz  + M[3];
        const float vc = M[5]*gy + M[6]*gz  + M[7];
        const float dc = M[9]*gy + M[10]*gz + M[11];
        const float u0 = M[0]*gxa + uc, u1 = M[0]*gxb + uc;
        const float v0 = M[4]*gxa + vc, v1 = M[4]*gxb + vc;
        const float d0 = M[8]*gxa + dc, d1 = M[8]*gxb + dc;
        const float dmin = fminf(d0, d1), dmax = fmaxf(d0, d1);
        if (dmax > DLO && dmin < DHI) {
            if (dmin >= DLO) {
                // d > 0 over whole tile => u/d, v/d monotone: endpoint hull exact
                const float ix0 = u0 / d0 * (59.0f/60.0f);
                const float ix1 = u1 / d1 * (59.0f/60.0f);
                const float iy0 = v0 / d0 * (27.0f/28.0f);
                const float iy1 = v1 / d1 * (27.0f/28.0f);
                pass = !(fmaxf(ix0, ix1) <= -1.002f || fminf(ix0, ix1) >= 60.002f ||
                         fmaxf(iy0, iy1) <= -1.002f || fminf(iy0, iy1) >= 28.002f);
            } else {
                pass = 1;  // d straddles DLO on tile: defer to per-lane test
            }
        }
    }

    // Deterministic compaction (warps 0..2 are exactly tid<96)
    unsigned ball = 0;
    int pos = 0;
    if (tid < 96) {
        ball = __ballot_sync(0xffffffffu, pass);
        if ((tid & 31) == 0) sm_wcnt[myw] = __popc(ball);
        pos = __popc(ball & ((1u << (tid & 31)) - 1u));
    }
    __syncthreads();
    const int cnt = sm_wcnt[0] + sm_wcnt[1] + sm_wcnt[2];
    if (tid < 96 && pass) {
        int off = 0;
        if (myw >= 1) off += sm_wcnt[0];
        if (myw >= 2) off += sm_wcnt[1];
        sm_list[off + pos] = tid;
    }
    __syncthreads();

    const int lane = tid & 31;
    const int cg   = tid >> 5;

    float acc[4][8];
    #pragma unroll
    for (int t = 0; t < 4; t++)
        #pragma unroll
        for (int j = 0; j < 8; j++) acc[t][j] = 0.0f;

    const float4* f4 = (const float4*)frustum;

    // ---- Phase 2: gather-accumulate over surviving (tile, combo) entries ----
    #pragma unroll 1
    for (int k = 0; k < cnt; k++) {
        const int e     = sm_list[k];
        const int combo = e >> 2;
        const int tile  = e & 3;
        const int cam   = combo >> 2;
        const int zz    = combo & 3;
        const float gz  = -3.0f + 2.0f * (float)zz;
        const float gx  = -47.625f + 0.75f * (float)(tile * 32 + lane);
        const float* M  = &sm_M[cam * 12];
        const float u   = M[0]*gx + M[1]*gy + M[2]*gz  + M[3];
        const float v   = M[4]*gx + M[5]*gy + M[6]*gz  + M[7];
        const float d   = M[8]*gx + M[9]*gy + M[10]*gz + M[11];
        const float rd  = 1.0f / d;
        const float ix  = u * rd * (59.0f/60.0f);
        const float iy  = v * rd * (27.0f/28.0f);
        const float iz  = (d - 2.0f) * (47.0f/48.0f);
        const bool ok = (ix > -1.0f) && (ix < 60.0f)
                     && (iy > -1.0f) && (iy < 28.0f)
                     && (iz > -1.0f) && (iz < 48.0f);
        if (!ok) continue;

        const float fx0 = floorf(ix); const int ix0 = (int)fx0; const float fx = ix - fx0;
        const float fy0 = floorf(iy); const int iy0 = (int)fy0; const float fy = iy - fy0;
        const float fz0 = floorf(iz); const int iz0 = (int)fz0; const float fz = iz - fz0;

        const float wx0 = (ix0 >= 0)      ? (1.0f - fx) : 0.0f;
        const float wx1 = (ix0 <= WW - 2) ? fx          : 0.0f;
        const float wy0 = (iy0 >= 0)      ? (1.0f - fy) : 0.0f;
        const float wy1 = (iy0 <= HH - 2) ? fy          : 0.0f;
        const float wz0 = (iz0 >= 0)      ? (1.0f - fz) : 0.0f;
        const float wz1 = (iz0 <= DD - 2) ? fz          : 0.0f;

        const int base = (b * NCAM + cam) * (DD * HH * WW);  // pixel units

        float tacc[8];
        #pragma unroll
        for (int j = 0; j < 8; j++) tacc[j] = 0.0f;

        #pragma unroll
        for (int dz = 0; dz < 2; dz++) {
            const float wz = dz ? wz1 : wz0;
            if (wz == 0.0f) continue;
            const int zoff = base + (iz0 + dz) * (HH * WW);
            #pragma unroll
            for (int dy = 0; dy < 2; dy++) {
                const float wzy = wz * (dy ? wy1 : wy0);
                if (wzy == 0.0f) continue;
                const int yoff = zoff + (iy0 + dy) * WW;
                #pragma unroll
                for (int dx = 0; dx < 2; dx++) {
                    const float w = wzy * (dx ? wx1 : wx0);
                    if (w == 0.0f) continue;
                    const int pix = yoff + (ix0 + dx);
                    const float4* p = f4 + (size_t)pix * (CC / 4) + cg * 2;
                    const float4 a = __ldg(p);
                    const float4 q = __ldg(p + 1);
                    tacc[0] += w * a.x; tacc[1] += w * a.y;
                    tacc[2] += w * a.z; tacc[3] += w * a.w;
                    tacc[4] += w * q.x; tacc[5] += w * q.y;
                    tacc[6] += w * q.z; tacc[7] += w * q.w;
                }
            }
        }

        // fold into the compile-time-indexed accumulator for this tile
        #pragma unroll
        for (int T = 0; T < 4; T++) {
            if (T == tile) {
                #pragma unroll
                for (int j = 0; j < 8; j++) acc[T][j] += tacc[j];
            }
        }
    }

    // ---- Phase 3: coalesced stores: out[b][c][y][x] ----
    #pragma unroll
    for (int T = 0; T < 4; T++) {
        const int xg = T * 32 + lane;
        size_t obase = (((size_t)b * CC + cg * 8) * GY + y) * GX + xg;
        #pragma unroll
        for (int j = 0; j < 8; j++) {
            out[obase + (size_t)j * (GY * GX)] = acc[T][j];
        }
    }
}

extern "C" void kernel_launch(void* const* d_in, const int* in_sizes, int n_in,
                              void* d_out, int out_size) {
    const float* frustum = (const float*)d_in[0];
    const float* intr    = (const float*)d_in[1];
    const float* l2s     = (const float*)d_in[2];
    float* out = (float*)d_out;

    dim3 grid(GY, BATCH);
    bev_kernel<<<grid, 256>>>(frustum, intr, l2s, out);
}

// round 8
// speedup vs baseline: 1.2655x; 1.2655x over previous
#include <cuda_runtime.h>
#include <cstdint>

// Problem constants
#define BATCH 2
#define NCAM  6
#define DD    48
#define HH    28
#define WW    60
#define CC    64
#define GX    128
#define GY    128

// Per-(b,cam) projection matrix M (3x4): uvd = M @ [gx,gy,gz,1]
__device__ float g_M[BATCH * NCAM * 12];

// ---------------------------------------------------------------------------
// Kernel 1: M = K @ inv(lidar_to_sensor)[0:3, :]   (12 tiny matrices)
// ---------------------------------------------------------------------------
__global__ void prep_kernel(const float* __restrict__ intr,
                            const float* __restrict__ l2s) {
    int t = threadIdx.x;
    if (t >= BATCH * NCAM) return;
    const float* m = l2s + t * 16;   // row-major 4x4
    const float* K = intr + t * 9;   // row-major 3x3

    float inv[16];
    inv[0]  =  m[5]*m[10]*m[15] - m[5]*m[11]*m[14] - m[9]*m[6]*m[15] + m[9]*m[7]*m[14] + m[13]*m[6]*m[11] - m[13]*m[7]*m[10];
    inv[4]  = -m[4]*m[10]*m[15] + m[4]*m[11]*m[14] + m[8]*m[6]*m[15] - m[8]*m[7]*m[14] - m[12]*m[6]*m[11] + m[12]*m[7]*m[10];
    inv[8]  =  m[4]*m[9]*m[15]  - m[4]*m[11]*m[13] - m[8]*m[5]*m[15] + m[8]*m[7]*m[13] + m[12]*m[5]*m[11] - m[12]*m[7]*m[9];
    inv[12] = -m[4]*m[9]*m[14]  + m[4]*m[10]*m[13] + m[8]*m[5]*m[14] - m[8]*m[6]*m[13] - m[12]*m[5]*m[10] + m[12]*m[6]*m[9];
    inv[1]  = -m[1]*m[10]*m[15] + m[1]*m[11]*m[14] + m[9]*m[2]*m[15] - m[9]*m[3]*m[14] - m[13]*m[2]*m[11] + m[13]*m[3]*m[10];
    inv[5]  =  m[0]*m[10]*m[15] - m[0]*m[11]*m[14] - m[8]*m[2]*m[15] + m[8]*m[3]*m[14] + m[12]*m[2]*m[11] - m[12]*m[3]*m[10];
    inv[9]  = -m[0]*m[9]*m[15]  + m[0]*m[11]*m[13] + m[8]*m[1]*m[15] - m[8]*m[3]*m[13] - m[12]*m[1]*m[11] + m[12]*m[3]*m[9];
    inv[13] =  m[0]*m[9]*m[14]  - m[0]*m[10]*m[13] - m[8]*m[1]*m[14] + m[8]*m[2]*m[13] + m[12]*m[1]*m[10] - m[12]*m[2]*m[9];
    inv[2]  =  m[1]*m[6]*m[15]  - m[1]*m[7]*m[14]  - m[5]*m[2]*m[15] + m[5]*m[3]*m[14] + m[13]*m[2]*m[7]  - m[13]*m[3]*m[6];
    inv[6]  = -m[0]*m[6]*m[15]  + m[0]*m[7]*m[14]  + m[4]*m[2]*m[15] - m[4]*m[3]*m[14] - m[12]*m[2]*m[7]  + m[12]*m[3]*m[6];
    inv[10] =  m[0]*m[5]*m[15]  - m[0]*m[7]*m[13]  - m[4]*m[1]*m[15] + m[4]*m[3]*m[13] + m[12]*m[1]*m[7]  - m[12]*m[3]*m[5];
    inv[14] = -m[0]*m[5]*m[14]  + m[0]*m[6]*m[13]  + m[4]*m[1]*m[14] - m[4]*m[2]*m[13] - m[12]*m[1]*m[6]  + m[12]*m[2]*m[5];
    inv[3]  = -m[1]*m[6]*m[11]  + m[1]*m[7]*m[10]  + m[5]*m[2]*m[11] - m[5]*m[3]*m[10] - m[9]*m[2]*m[7]   + m[9]*m[3]*m[6];
    inv[7]  =  m[0]*m[6]*m[11]  - m[0]*m[7]*m[10]  - m[4]*m[2]*m[11] + m[4]*m[3]*m[10] + m[8]*m[2]*m[7]   - m[8]*m[3]*m[6];
    inv[11] = -m[0]*m[5]*m[11]  + m[0]*m[7]*m[9]   + m[4]*m[1]*m[11] - m[4]*m[3]*m[9]  - m[8]*m[1]*m[7]   + m[8]*m[3]*m[5];
    inv[15] =  m[0]*m[5]*m[10]  - m[0]*m[6]*m[9]   - m[4]*m[1]*m[10] + m[4]*m[2]*m[9]  + m[8]*m[1]*m[6]   - m[8]*m[2]*m[5];

    float det = m[0]*inv[0] + m[1]*inv[4] + m[2]*inv[8] + m[3]*inv[12];
    float rdet = 1.0f / det;
    #pragma unroll
    for (int i = 0; i < 16; i++) inv[i] *= rdet;

    float* M = g_M + t * 12;
    #pragma unroll
    for (int r = 0; r < 3; r++) {
        #pragma unroll
        for (int c = 0; c < 4; c++) {
            M[r * 4 + c] = K[r*3 + 0] * inv[0*4 + c]
                         + K[r*3 + 1] * inv[1*4 + c]
                         + K[r*3 + 2] * inv[2*4 + c];
        }
    }
}

// ---------------------------------------------------------------------------
// Kernel 2: BEV splat. Grid: (GX/32, GY, BATCH) = 1024 blocks, 256 threads.
//   warp (tid>>5) = channel group cg (channels cg*8..cg*8+7)
//   lane (tid&31) = x within the block's 32-wide tile
//
// Step 1: 24 threads run the exact endpoint-hull interval test for this
//         tile x (cam,z) combo -> 24-bit validity mask (single ballot).
//         (u,v,d are affine in gx; when d>0 on the tile, u/d & v/d are
//          monotone Mobius functions, so endpoint evaluation is an exact
//          hull; d straddling the low cut conservatively passes.)
// Step 2: if mask empty (common case) -> store zeros. Otherwise iterate set
//         bits (ascending => deterministic FP order): per-lane projection +
//         trilinear gather, accumulate 8 channels in registers.
// Step 3: coalesced stores out[b][c][y][x].
// ---------------------------------------------------------------------------
__global__ void __launch_bounds__(256)
bev_kernel(const float* __restrict__ frustum, float* __restrict__ out) {
    __shared__ float sm_M[NCAM * 12];
    __shared__ unsigned sm_mask;

    const int tid = threadIdx.x;
    const int b   = blockIdx.z;
    const int y   = blockIdx.y;
    const int x0t = blockIdx.x * 32;

    if (tid < NCAM * 12) sm_M[tid] = g_M[b * NCAM * 12 + tid];
    __syncthreads();

    const float gy = -47.625f + 0.75f * (float)y;

    // ---- Step 1: interval validity test (threads 0..23, one combo each) ----
    // d bounds: need iz in (-1,48) => d in (2-48/47, 2+48*48/47); widened.
    const float DLO = 0.9770f;
    const float DHI = 51.05f;

    int pass = 0;
    if (tid < 32) {
        if (tid < 24) {
            const int cam = tid >> 2;
            const int zz  = tid & 3;
            const float gz  = -3.0f + 2.0f * (float)zz;
            const float* M  = &sm_M[cam * 12];
            const float gxa = -47.625f + 0.75f * (float)(x0t);
            const float gxb = -47.625f + 0.75f * (float)(x0t + 31);
            const float uc = M[1]*gy + M[2]*gz  + M[3];
            const float vc = M[5]*gy + M[6]*gz  + M[7];
            const float dc = M[9]*gy + M[10]*gz + M[11];
            const float u0 = M[0]*gxa + uc, u1 = M[0]*gxb + uc;
            const float v0 = M[4]*gxa + vc, v1 = M[4]*gxb + vc;
            const float d0 = M[8]*gxa + dc, d1 = M[8]*gxb + dc;
            const float dmin = fminf(d0, d1), dmax = fmaxf(d0, d1);
            if (dmax > DLO && dmin < DHI) {
                if (dmin >= DLO) {
                    const float ix0 = u0 / d0 * (59.0f/60.0f);
                    const float ix1 = u1 / d1 * (59.0f/60.0f);
                    const float iy0 = v0 / d0 * (27.0f/28.0f);
                    const float iy1 = v1 / d1 * (27.0f/28.0f);
                    pass = !(fmaxf(ix0, ix1) <= -1.002f || fminf(ix0, ix1) >= 60.002f ||
                             fmaxf(iy0, iy1) <= -1.002f || fminf(iy0, iy1) >= 28.002f);
                } else {
                    pass = 1;  // d straddles the low cut: defer to per-lane test
                }
            }
        }
        const unsigned ball = __ballot_sync(0xffffffffu, pass);
        if (tid == 0) sm_mask = ball;
    }
    __syncthreads();

    const int lane = tid & 31;
    const int cg   = tid >> 5;

    float acc[8];
    #pragma unroll
    for (int j = 0; j < 8; j++) acc[j] = 0.0f;

    unsigned m = sm_mask;
    if (m) {
        const float4* f4 = (const float4*)frustum;
        const float gx = -47.625f + 0.75f * (float)(x0t + lane);

        // ---- Step 2: gather-accumulate over surviving combos ----
        #pragma unroll 1
        while (m) {
            const int combo = __ffs(m) - 1;   // ascending: deterministic order
            m &= m - 1;
            const int cam = combo >> 2;
            const int zz  = combo & 3;
            const float gz = -3.0f + 2.0f * (float)zz;
            const float* M = &sm_M[cam * 12];
            const float u  = M[0]*gx + M[1]*gy + M[2]*gz  + M[3];
            const float v  = M[4]*gx + M[5]*gy + M[6]*gz  + M[7];
            const float d  = M[8]*gx + M[9]*gy + M[10]*gz + M[11];
            const float rd = 1.0f / d;
            const float ix = u * rd * (59.0f/60.0f);
            const float iy = v * rd * (27.0f/28.0f);
            const float iz = (d - 2.0f) * (47.0f/48.0f);
            const bool ok = (ix > -1.0f) && (ix < 60.0f)
                         && (iy > -1.0f) && (iy < 28.0f)
                         && (iz > -1.0f) && (iz < 48.0f);
            if (!ok) continue;

            const float fx0 = floorf(ix); const int ix0 = (int)fx0; const float fx = ix - fx0;
            const float fy0 = floorf(iy); const int iy0 = (int)fy0; const float fy = iy - fy0;
            const float fz0 = floorf(iz); const int iz0 = (int)fz0; const float fz = iz - fz0;

            const float wx0 = (ix0 >= 0)      ? (1.0f - fx) : 0.0f;
            const float wx1 = (ix0 <= WW - 2) ? fx          : 0.0f;
            const float wy0 = (iy0 >= 0)      ? (1.0f - fy) : 0.0f;
            const float wy1 = (iy0 <= HH - 2) ? fy          : 0.0f;
            const float wz0 = (iz0 >= 0)      ? (1.0f - fz) : 0.0f;
            const float wz1 = (iz0 <= DD - 2) ? fz          : 0.0f;

            const int base = (b * NCAM + cam) * (DD * HH * WW);  // pixel units

            #pragma unroll
            for (int dz = 0; dz < 2; dz++) {
                const float wz = dz ? wz1 : wz0;
                if (wz == 0.0f) continue;
                const int zoff = base + (iz0 + dz) * (HH * WW);
                #pragma unroll
                for (int dy = 0; dy < 2; dy++) {
                    const float wzy = wz * (dy ? wy1 : wy0);
                    if (wzy == 0.0f) continue;
                    const int yoff = zoff + (iy0 + dy) * WW;
                    #pragma unroll
                    for (int dx = 0; dx < 2; dx++) {
                        const float w = wzy * (dx ? wx1 : wx0);
                        if (w == 0.0f) continue;
                        const int pix = yoff + (ix0 + dx);
                        const float4* p = f4 + (size_t)pix * (CC / 4) + cg * 2;
                        const float4 a = __ldg(p);
                        const float4 q = __ldg(p + 1);
                        acc[0] += w * a.x; acc[1] += w * a.y;
                        acc[2] += w * a.z; acc[3] += w * a.w;
                        acc[4] += w * q.x; acc[5] += w * q.y;
                        acc[6] += w * q.z; acc[7] += w * q.w;
                    }
                }
            }
        }
    }

    // ---- Step 3: coalesced stores: out[b][c][y][x] ----
    const int xg = x0t + lane;
    size_t obase = (((size_t)b * CC + cg * 8) * GY + y) * GX + xg;
    #pragma unroll
    for (int j = 0; j < 8; j++) {
        out[obase + (size_t)j * (GY * GX)] = acc[j];
    }
}

extern "C" void kernel_launch(void* const* d_in, const int* in_sizes, int n_in,
                              void* d_out, int out_size) {
    const float* frustum = (const float*)d_in[0];
    const float* intr    = (const float*)d_in[1];
    const float* l2s     = (const float*)d_in[2];
    float* out = (float*)d_out;

    prep_kernel<<<1, 32>>>(intr, l2s);
    dim3 grid(GX / 32, GY, BATCH);
    bev_kernel<<<grid, 256>>>(frustum, out);
}

// round 9
// speedup vs baseline: 1.5917x; 1.2578x over previous
#include <cuda_runtime.h>
#include <cstdint>

// Problem constants
#define BATCH 2
#define NCAM  6
#define DD    48
#define HH    28
#define WW    60
#define CC    64
#define GX    128
#define GY    128

// ---------------------------------------------------------------------------
// Single fused kernel. Grid: (GX/32, GY, BATCH) = 1024 blocks, 512 threads.
//   warp (tid>>5) = channel group cg (channels cg*4..cg*4+3), cg in 0..15
//   lane (tid&31) = x within the block's 32-wide tile
//
// Warp 0 only (no other warp does setup work):
//   - all 32 lanes redundantly compute M = K @ inv(l2s)[0:3,:] for cam =
//     min(lane,5) (SIMT: same latency as 6 lanes); lanes 0..5 write sm_M
//   - lanes 0..23 run the exact endpoint-hull interval test for combo =
//     lane (cam*4+z), fetching M[cam] via register shuffles
//   - single ballot -> 24-bit validity mask -> sm_mask
// One __syncthreads. Then every thread: if mask empty (vast majority of
// blocks) store zeros; else iterate set bits ascending (deterministic FP
// order), per-lane projection + trilinear gather of its 4 channels.
// ---------------------------------------------------------------------------
__global__ void __launch_bounds__(512)
bev_kernel(const float* __restrict__ frustum,
           const float* __restrict__ intr,
           const float* __restrict__ l2s,
           float* __restrict__ out) {
    __shared__ float sm_M[NCAM * 12];
    __shared__ unsigned sm_mask;

    const int tid = threadIdx.x;
    const int b   = blockIdx.z;
    const int y   = blockIdx.y;
    const int x0t = blockIdx.x * 32;

    const float gy = -47.625f + 0.75f * (float)y;

    if (tid < 32) {
        const int lane = tid;
        // ---- inverse + M, computed by all lanes for cam = min(lane,5) ----
        const int camL = lane < 6 ? lane : 5;
        const int idx  = b * NCAM + camL;
        const float* m = l2s + idx * 16;   // row-major 4x4
        const float* K = intr + idx * 9;   // row-major 3x3

        float inv[16];
        inv[0]  =  m[5]*m[10]*m[15] - m[5]*m[11]*m[14] - m[9]*m[6]*m[15] + m[9]*m[7]*m[14] + m[13]*m[6]*m[11] - m[13]*m[7]*m[10];
        inv[4]  = -m[4]*m[10]*m[15] + m[4]*m[11]*m[14] + m[8]*m[6]*m[15] - m[8]*m[7]*m[14] - m[12]*m[6]*m[11] + m[12]*m[7]*m[10];
        inv[8]  =  m[4]*m[9]*m[15]  - m[4]*m[11]*m[13] - m[8]*m[5]*m[15] + m[8]*m[7]*m[13] + m[12]*m[5]*m[11] - m[12]*m[7]*m[9];
        inv[12] = -m[4]*m[9]*m[14]  + m[4]*m[10]*m[13] + m[8]*m[5]*m[14] - m[8]*m[6]*m[13] - m[12]*m[5]*m[10] + m[12]*m[6]*m[9];
        inv[1]  = -m[1]*m[10]*m[15] + m[1]*m[11]*m[14] + m[9]*m[2]*m[15] - m[9]*m[3]*m[14] - m[13]*m[2]*m[11] + m[13]*m[3]*m[10];
        inv[5]  =  m[0]*m[10]*m[15] - m[0]*m[11]*m[14] - m[8]*m[2]*m[15] + m[8]*m[3]*m[14] + m[12]*m[2]*m[11] - m[12]*m[3]*m[10];
        inv[9]  = -m[0]*m[9]*m[15]  + m[0]*m[11]*m[13] + m[8]*m[1]*m[15] - m[8]*m[3]*m[13] - m[12]*m[1]*m[11] + m[12]*m[3]*m[9];
        inv[13] =  m[0]*m[9]*m[14]  - m[0]*m[10]*m[13] - m[8]*m[1]*m[14] + m[8]*m[2]*m[13] + m[12]*m[1]*m[10] - m[12]*m[2]*m[9];
        inv[2]  =  m[1]*m[6]*m[15]  - m[1]*m[7]*m[14]  - m[5]*m[2]*m[15] + m[5]*m[3]*m[14] + m[13]*m[2]*m[7]  - m[13]*m[3]*m[6];
        inv[6]  = -m[0]*m[6]*m[15]  + m[0]*m[7]*m[14]  + m[4]*m[2]*m[15] - m[4]*m[3]*m[14] - m[12]*m[2]*m[7]  + m[12]*m[3]*m[6];
        inv[10] =  m[0]*m[5]*m[15]  - m[0]*m[7]*m[13]  - m[4]*m[1]*m[15] + m[4]*m[3]*m[13] + m[12]*m[1]*m[7]  - m[12]*m[3]*m[5];
        inv[14] = -m[0]*m[5]*m[14]  + m[0]*m[6]*m[13]  + m[4]*m[1]*m[14] - m[4]*m[2]*m[13] - m[12]*m[1]*m[6]  + m[12]*m[2]*m[5];
        inv[3]  = -m[1]*m[6]*m[11]  + m[1]*m[7]*m[10]  + m[5]*m[2]*m[11] - m[5]*m[3]*m[10] - m[9]*m[2]*m[7]   + m[9]*m[3]*m[6];
        inv[7]  =  m[0]*m[6]*m[11]  - m[0]*m[7]*m[10]  - m[4]*m[2]*m[11] + m[4]*m[3]*m[10] + m[8]*m[2]*m[7]   - m[8]*m[3]*m[6];
        inv[11] = -m[0]*m[5]*m[11]  + m[0]*m[7]*m[9]   + m[4]*m[1]*m[11] - m[4]*m[3]*m[9]  - m[8]*m[1]*m[7]   + m[8]*m[3]*m[5];
        inv[15] =  m[0]*m[5]*m[10]  - m[0]*m[6]*m[9]   - m[4]*m[1]*m[10] + m[4]*m[2]*m[9]  + m[8]*m[1]*m[6]   - m[8]*m[2]*m[5];

        float det = m[0]*inv[0] + m[1]*inv[4] + m[2]*inv[8] + m[3]*inv[12];
        float rdet = 1.0f / det;
        #pragma unroll
        for (int i = 0; i < 16; i++) inv[i] *= rdet;

        float Mr[12];
        #pragma unroll
        for (int r = 0; r < 3; r++) {
            #pragma unroll
            for (int c = 0; c < 4; c++) {
                Mr[r * 4 + c] = K[r*3 + 0] * inv[0*4 + c]
                              + K[r*3 + 1] * inv[1*4 + c]
                              + K[r*3 + 2] * inv[2*4 + c];
            }
        }
        if (lane < 6) {
            #pragma unroll
            for (int i = 0; i < 12; i++) sm_M[lane * 12 + i] = Mr[i];
        }

        // ---- interval validity test: lanes 0..23, combo = lane ----
        const int cam = lane >> 2;     // valid for lane < 24
        float Ms[12];
        #pragma unroll
        for (int i = 0; i < 12; i++)
            Ms[i] = __shfl_sync(0xffffffffu, Mr[i], cam < 6 ? cam : 0);

        int pass = 0;
        if (lane < 24) {
            const int zz  = lane & 3;
            const float gz  = -3.0f + 2.0f * (float)zz;
            const float gxa = -47.625f + 0.75f * (float)(x0t);
            const float gxb = -47.625f + 0.75f * (float)(x0t + 31);
            const float DLO = 0.9770f;   // d > 2 - 48/47, widened
            const float DHI = 51.05f;    // d < 2 + 48*48/47, widened
            const float uc = Ms[1]*gy + Ms[2]*gz  + Ms[3];
            const float vc = Ms[5]*gy + Ms[6]*gz  + Ms[7];
            const float dc = Ms[9]*gy + Ms[10]*gz + Ms[11];
            const float u0 = Ms[0]*gxa + uc, u1 = Ms[0]*gxb + uc;
            const float v0 = Ms[4]*gxa + vc, v1 = Ms[4]*gxb + vc;
            const float d0 = Ms[8]*gxa + dc, d1 = Ms[8]*gxb + dc;
            const float dmin = fminf(d0, d1), dmax = fmaxf(d0, d1);
            if (dmax > DLO && dmin < DHI) {
                if (dmin >= DLO) {
                    // d > 0 on tile => u/d, v/d monotone: endpoint hull exact
                    const float ix0 = u0 / d0 * (59.0f/60.0f);
                    const float ix1 = u1 / d1 * (59.0f/60.0f);
                    const float iy0 = v0 / d0 * (27.0f/28.0f);
                    const float iy1 = v1 / d1 * (27.0f/28.0f);
                    pass = !(fmaxf(ix0, ix1) <= -1.002f || fminf(ix0, ix1) >= 60.002f ||
                             fmaxf(iy0, iy1) <= -1.002f || fminf(iy0, iy1) >= 28.002f);
                } else {
                    pass = 1;  // d straddles low cut: defer to per-lane test
                }
            }
        }
        const unsigned ball = __ballot_sync(0xffffffffu, pass);
        if (lane == 0) sm_mask = ball;
    }
    __syncthreads();

    const int lane = tid & 31;
    const int cg   = tid >> 5;           // 0..15, 4 channels each

    float acc[4];
    acc[0] = acc[1] = acc[2] = acc[3] = 0.0f;

    unsigned mk = sm_mask;
    if (mk) {
        const float4* f4 = (const float4*)frustum;
        const float gx = -47.625f + 0.75f * (float)(x0t + lane);

        // ---- gather-accumulate over surviving combos (ascending order) ----
        #pragma unroll 1
        while (mk) {
            const int combo = __ffs(mk) - 1;
            mk &= mk - 1;
            const int cam = combo >> 2;
            const int zz  = combo & 3;
            const float gz = -3.0f + 2.0f * (float)zz;
            const float* M = &sm_M[cam * 12];
            const float u  = M[0]*gx + M[1]*gy + M[2]*gz  + M[3];
            const float v  = M[4]*gx + M[5]*gy + M[6]*gz  + M[7];
            const float d  = M[8]*gx + M[9]*gy + M[10]*gz + M[11];
            const float rd = 1.0f / d;
            const float ix = u * rd * (59.0f/60.0f);
            const float iy = v * rd * (27.0f/28.0f);
            const float iz = (d - 2.0f) * (47.0f/48.0f);
            const bool ok = (ix > -1.0f) && (ix < 60.0f)
                         && (iy > -1.0f) && (iy < 28.0f)
                         && (iz > -1.0f) && (iz < 48.0f);
            if (!ok) continue;

            const float fx0 = floorf(ix); const int ix0 = (int)fx0; const float fx = ix - fx0;
            const float fy0 = floorf(iy); const int iy0 = (int)fy0; const float fy = iy - fy0;
            const float fz0 = floorf(iz); const int iz0 = (int)fz0; const float fz = iz - fz0;

            const float wx0 = (ix0 >= 0)      ? (1.0f - fx) : 0.0f;
            const float wx1 = (ix0 <= WW - 2) ? fx          : 0.0f;
            const float wy0 = (iy0 >= 0)      ? (1.0f - fy) : 0.0f;
            const float wy1 = (iy0 <= HH - 2) ? fy          : 0.0f;
            const float wz0 = (iz0 >= 0)      ? (1.0f - fz) : 0.0f;
            const float wz1 = (iz0 <= DD - 2) ? fz          : 0.0f;

            const int base = (b * NCAM + cam) * (DD * HH * WW);  // pixel units

            #pragma unroll
            for (int dz = 0; dz < 2; dz++) {
                const float wz = dz ? wz1 : wz0;
                if (wz == 0.0f) continue;
                const int zoff = base + (iz0 + dz) * (HH * WW);
                #pragma unroll
                for (int dy = 0; dy < 2; dy++) {
                    const float wzy = wz * (dy ? wy1 : wy0);
                    if (wzy == 0.0f) continue;
                    const int yoff = zoff + (iy0 + dy) * WW;
                    #pragma unroll
                    for (int dx = 0; dx < 2; dx++) {
                        const float w = wzy * (dx ? wx1 : wx0);
                        if (w == 0.0f) continue;
                        const int pix = yoff + (ix0 + dx);
                        const float4 a = __ldg(f4 + (size_t)pix * (CC / 4) + cg);
                        acc[0] += w * a.x; acc[1] += w * a.y;
                        acc[2] += w * a.z; acc[3] += w * a.w;
                    }
                }
            }
        }
    }

    // ---- coalesced stores: out[b][c][y][x] ----
    const int xg = x0t + lane;
    size_t obase = (((size_t)b * CC + cg * 4) * GY + y) * GX + xg;
    #pragma unroll
    for (int j = 0; j < 4; j++) {
        out[obase + (size_t)j * (GY * GX)] = acc[j];
    }
}

extern "C" void kernel_launch(void* const* d_in, const int* in_sizes, int n_in,
                              void* d_out, int out_size) {
    const float* frustum = (const float*)d_in[0];
    const float* intr    = (const float*)d_in[1];
    const float* l2s     = (const float*)d_in[2];
    float* out = (float*)d_out;

    dim3 grid(GX / 32, GY, BATCH);
    bev_kernel<<<grid, 512>>>(frustum, intr, l2s, out);
}

// round 10
// speedup vs baseline: 1.7457x; 1.0968x over previous
#include <cuda_runtime.h>
#include <cstdint>

// Problem constants
#define BATCH 2
#define NCAM  6
#define DD    48
#define HH    28
#define WW    60
#define CC    64
#define GX    128
#define GY    128

// ---------------------------------------------------------------------------
// Single fused kernel. Grid: (GX/32, GY, BATCH) = 1024 blocks, 512 threads.
//   warp (tid>>5) = channel group cg (channels cg*4..cg*4+3), cg in 0..15
//   lane (tid&31) = x within the block's 32-wide tile
//
// Warp 0 only:
//   - all 32 lanes redundantly compute M = K @ inv(l2s)[0:3,:] for cam =
//     min(lane,5); lanes 0..5 write sm_M
//   - lanes 0..23 run an EXACT, divide-free interval validity test for
//     combo = lane (cam*4+z):
//       * u,v,d are affine in gx over the 32-wide tile
//       * if d crosses DLO inside the tile, the sub-DLO endpoint is replaced
//         by the (linear-exact) crossing point -> test the valid sub-interval
//       * with d>0, bound tests multiply through by d (affine, endpoint-exact)
//   - single ballot -> 24-bit validity mask -> sm_mask
// One __syncthreads. Then: mask empty (vast majority) -> store zeros; else
// iterate set bits ascending (deterministic FP order), per-lane projection +
// trilinear gather of 4 channels per thread.
// ---------------------------------------------------------------------------
__global__ void __launch_bounds__(512)
bev_kernel(const float* __restrict__ frustum,
           const float* __restrict__ intr,
           const float* __restrict__ l2s,
           float* __restrict__ out) {
    __shared__ float sm_M[NCAM * 12];
    __shared__ unsigned sm_mask;

    const int tid = threadIdx.x;
    const int b   = blockIdx.z;
    const int y   = blockIdx.y;
    const int x0t = blockIdx.x * 32;

    const float gy = -47.625f + 0.75f * (float)y;

    if (tid < 32) {
        const int lane = tid;
        // ---- inverse + M, computed by all lanes for cam = min(lane,5) ----
        const int camL = lane < 6 ? lane : 5;
        const int idx  = b * NCAM + camL;
        const float* m = l2s + idx * 16;   // row-major 4x4
        const float* K = intr + idx * 9;   // row-major 3x3

        float inv[16];
        inv[0]  =  m[5]*m[10]*m[15] - m[5]*m[11]*m[14] - m[9]*m[6]*m[15] + m[9]*m[7]*m[14] + m[13]*m[6]*m[11] - m[13]*m[7]*m[10];
        inv[4]  = -m[4]*m[10]*m[15] + m[4]*m[11]*m[14] + m[8]*m[6]*m[15] - m[8]*m[7]*m[14] - m[12]*m[6]*m[11] + m[12]*m[7]*m[10];
        inv[8]  =  m[4]*m[9]*m[15]  - m[4]*m[11]*m[13] - m[8]*m[5]*m[15] + m[8]*m[7]*m[13] + m[12]*m[5]*m[11] - m[12]*m[7]*m[9];
        inv[12] = -m[4]*m[9]*m[14]  + m[4]*m[10]*m[13] + m[8]*m[5]*m[14] - m[8]*m[6]*m[13] - m[12]*m[5]*m[10] + m[12]*m[6]*m[9];
        inv[1]  = -m[1]*m[10]*m[15] + m[1]*m[11]*m[14] + m[9]*m[2]*m[15] - m[9]*m[3]*m[14] - m[13]*m[2]*m[11] + m[13]*m[3]*m[10];
        inv[5]  =  m[0]*m[10]*m[15] - m[0]*m[11]*m[14] - m[8]*m[2]*m[15] + m[8]*m[3]*m[14] + m[12]*m[2]*m[11] - m[12]*m[3]*m[10];
        inv[9]  = -m[0]*m[9]*m[15]  + m[0]*m[11]*m[13] + m[8]*m[1]*m[15] - m[8]*m[3]*m[13] - m[12]*m[1]*m[11] + m[12]*m[3]*m[9];
        inv[13] =  m[0]*m[9]*m[14]  - m[0]*m[10]*m[13] - m[8]*m[1]*m[14] + m[8]*m[2]*m[13] + m[12]*m[1]*m[10] - m[12]*m[2]*m[9];
        inv[2]  =  m[1]*m[6]*m[15]  - m[1]*m[7]*m[14]  - m[5]*m[2]*m[15] + m[5]*m[3]*m[14] + m[13]*m[2]*m[7]  - m[13]*m[3]*m[6];
        inv[6]  = -m[0]*m[6]*m[15]  + m[0]*m[7]*m[14]  + m[4]*m[2]*m[15] - m[4]*m[3]*m[14] - m[12]*m[2]*m[7]  + m[12]*m[3]*m[6];
        inv[10] =  m[0]*m[5]*m[15]  - m[0]*m[7]*m[13]  - m[4]*m[1]*m[15] + m[4]*m[3]*m[13] + m[12]*m[1]*m[7]  - m[12]*m[3]*m[5];
        inv[14] = -m[0]*m[5]*m[14]  + m[0]*m[6]*m[13]  + m[4]*m[1]*m[14] - m[4]*m[2]*m[13] - m[12]*m[1]*m[6]  + m[12]*m[2]*m[5];
        inv[3]  = -m[1]*m[6]*m[11]  + m[1]*m[7]*m[10]  + m[5]*m[2]*m[11] - m[5]*m[3]*m[10] - m[9]*m[2]*m[7]   + m[9]*m[3]*m[6];
        inv[7]  =  m[0]*m[6]*m[11]  - m[0]*m[7]*m[10]  - m[4]*m[2]*m[11] + m[4]*m[3]*m[10] + m[8]*m[2]*m[7]   - m[8]*m[3]*m[6];
        inv[11] = -m[0]*m[5]*m[11]  + m[0]*m[7]*m[9]   + m[4]*m[1]*m[11] - m[4]*m[3]*m[9]  - m[8]*m[1]*m[7]   + m[8]*m[3]*m[5];
        inv[15] =  m[0]*m[5]*m[10]  - m[0]*m[6]*m[9]   - m[4]*m[1]*m[10] + m[4]*m[2]*m[9]  + m[8]*m[1]*m[6]   - m[8]*m[2]*m[5];

        float det = m[0]*inv[0] + m[1]*inv[4] + m[2]*inv[8] + m[3]*inv[12];
        float rdet = 1.0f / det;
        #pragma unroll
        for (int i = 0; i < 16; i++) inv[i] *= rdet;

        float Mr[12];
        #pragma unroll
        for (int r = 0; r < 3; r++) {
            #pragma unroll
            for (int c = 0; c < 4; c++) {
                Mr[r * 4 + c] = K[r*3 + 0] * inv[0*4 + c]
                              + K[r*3 + 1] * inv[1*4 + c]
                              + K[r*3 + 2] * inv[2*4 + c];
            }
        }
        if (lane < 6) {
            #pragma unroll
            for (int i = 0; i < 12; i++) sm_M[lane * 12 + i] = Mr[i];
        }

        // ---- exact interval validity test: lanes 0..23, combo = lane ----
        const int cam = lane >> 2;     // valid for lane < 24
        float Ms[12];
        #pragma unroll
        for (int i = 0; i < 12; i++)
            Ms[i] = __shfl_sync(0xffffffffu, Mr[i], cam < 6 ? cam : 0);

        int pass = 0;
        if (lane < 24) {
            const int zz  = lane & 3;
            const float gz  = -3.0f + 2.0f * (float)zz;
            const float gxa = -47.625f + 0.75f * (float)(x0t);
            const float gxb = -47.625f + 0.75f * (float)(x0t + 31);
            const float DLO = 0.9770f;   // d > 2 - 48/47, widened down
            const float DHI = 51.05f;    // d < 2 + 48*48/47, widened up
            const float uc = Ms[1]*gy + Ms[2]*gz  + Ms[3];
            const float vc = Ms[5]*gy + Ms[6]*gz  + Ms[7];
            const float dc = Ms[9]*gy + Ms[10]*gz + Ms[11];
            float u0 = Ms[0]*gxa + uc, u1 = Ms[0]*gxb + uc;
            float v0 = Ms[4]*gxa + vc, v1 = Ms[4]*gxb + vc;
            float d0 = Ms[8]*gxa + dc, d1 = Ms[8]*gxb + dc;
            const float dmin = fminf(d0, d1), dmax = fmaxf(d0, d1);
            if (dmax > DLO && dmin < DHI) {
                if (dmin < DLO) {
                    // d crosses DLO inside the tile. u,v,d affine in gx =>
                    // linear interpolation gives the EXACT crossing point;
                    // restrict the hull to the valid sub-interval d >= DLO.
                    const float t  = (DLO - d0) / (d1 - d0);
                    const float uX = u0 + t * (u1 - u0);
                    const float vX = v0 + t * (v1 - v0);
                    if (d0 < DLO) { u0 = uX; v0 = vX; d0 = DLO; }
                    else          { u1 = uX; v1 = vX; d1 = DLO; }
                }
                // d > 0 on the (sub)interval: multiply bound tests through
                // by d; each is affine in gx => endpoint evaluation exact.
                const float sx = 59.0f / 60.0f, sy = 27.0f / 28.0f;
                const float a0 = sx * u0, a1 = sx * u1;
                const float e0 = sy * v0, e1 = sy * v1;
                const bool rej =
                    (fmaxf(a0 + 1.002f  * d0, a1 + 1.002f  * d1) <= 0.0f) ||
                    (fminf(a0 - 60.002f * d0, a1 - 60.002f * d1) >= 0.0f) ||
                    (fmaxf(e0 + 1.002f  * d0, e1 + 1.002f  * d1) <= 0.0f) ||
                    (fminf(e0 - 28.002f * d0, e1 - 28.002f * d1) >= 0.0f);
                pass = !rej;
            }
        }
        const unsigned ball = __ballot_sync(0xffffffffu, pass);
        if (lane == 0) sm_mask = ball;
    }
    __syncthreads();

    const int lane = tid & 31;
    const int cg   = tid >> 5;           // 0..15, 4 channels each

    float acc[4];
    acc[0] = acc[1] = acc[2] = acc[3] = 0.0f;

    unsigned mk = sm_mask;
    if (mk) {
        const float4* f4 = (const float4*)frustum;
        const float gx = -47.625f + 0.75f * (float)(x0t + lane);

        // ---- gather-accumulate over surviving combos (ascending order) ----
        #pragma unroll 1
        while (mk) {
            const int combo = __ffs(mk) - 1;
            mk &= mk - 1;
            const int cam = combo >> 2;
            const int zz  = combo & 3;
            const float gz = -3.0f + 2.0f * (float)zz;
            const float* M = &sm_M[cam * 12];
            const float u  = M[0]*gx + M[1]*gy + M[2]*gz  + M[3];
            const float v  = M[4]*gx + M[5]*gy + M[6]*gz  + M[7];
            const float d  = M[8]*gx + M[9]*gy + M[10]*gz + M[11];
            const float rd = 1.0f / d;
            const float ix = u * rd * (59.0f/60.0f);
            const float iy = v * rd * (27.0f/28.0f);
            const float iz = (d - 2.0f) * (47.0f/48.0f);
            const bool ok = (ix > -1.0f) && (ix < 60.0f)
                         && (iy > -1.0f) && (iy < 28.0f)
                         && (iz > -1.0f) && (iz < 48.0f);
            if (!ok) continue;

            const float fx0 = floorf(ix); const int ix0 = (int)fx0; const float fx = ix - fx0;
            const float fy0 = floorf(iy); const int iy0 = (int)fy0; const float fy = iy - fy0;
            const float fz0 = floorf(iz); const int iz0 = (int)fz0; const float fz = iz - fz0;

            const float wx0 = (ix0 >= 0)      ? (1.0f - fx) : 0.0f;
            const float wx1 = (ix0 <= WW - 2) ? fx          : 0.0f;
            const float wy0 = (iy0 >= 0)      ? (1.0f - fy) : 0.0f;
            const float wy1 = (iy0 <= HH - 2) ? fy          : 0.0f;
            const float wz0 = (iz0 >= 0)      ? (1.0f - fz) : 0.0f;
            const float wz1 = (iz0 <= DD - 2) ? fz          : 0.0f;

            const int base = (b * NCAM + cam) * (DD * HH * WW);  // pixel units

            #pragma unroll
            for (int dz = 0; dz < 2; dz++) {
                const float wz = dz ? wz1 : wz0;
                if (wz == 0.0f) continue;
                const int zoff = base + (iz0 + dz) * (HH * WW);
                #pragma unroll
                for (int dy = 0; dy < 2; dy++) {
                    const float wzy = wz * (dy ? wy1 : wy0);
                    if (wzy == 0.0f) continue;
                    const int yoff = zoff + (iy0 + dy) * WW;
                    #pragma unroll
                    for (int dx = 0; dx < 2; dx++) {
                        const float w = wzy * (dx ? wx1 : wx0);
                        if (w == 0.0f) continue;
                        const int pix = yoff + (ix0 + dx);
                        const float4 a = __ldg(f4 + (size_t)pix * (CC / 4) + cg);
                        acc[0] += w * a.x; acc[1] += w * a.y;
                        acc[2] += w * a.z; acc[3] += w * a.w;
                    }
                }
            }
        }
    }

    // ---- coalesced stores: out[b][c][y][x] ----
    const int xg = x0t + lane;
    size_t obase = (((size_t)b * CC + cg * 4) * GY + y) * GX + xg;
    #pragma unroll
    for (int j = 0; j < 4; j++) {
        out[obase + (size_t)j * (GY * GX)] = acc[j];
    }
}

extern "C" void kernel_launch(void* const* d_in, const int* in_sizes, int n_in,
                              void* d_out, int out_size) {
    const float* frustum = (const float*)d_in[0];
    const float* intr    = (const float*)d_in[1];
    const float* l2s     = (const float*)d_in[2];
    float* out = (float*)d_out;

    dim3 grid(GX / 32, GY, BATCH);
    bev_kernel<<<grid, 512>>>(frustum, intr, l2s, out);
}